// round 11
// baseline (speedup 1.0000x reference)
#include <cuda_runtime.h>
#include <cstdint>
#include <math.h>

#define E_EXPERTS 5
#define CDIM      256
#define HALF      128
#define QUART     64
#define BDIM      8
#define NPIX      6400
#define PIX       64

typedef uint32_t u32;
typedef uint16_t u16;

__device__ int   g_expert[BDIM];
__device__ float g_pooled[BDIM * CDIM];

// ---------- fp16 helpers ----------
__device__ __forceinline__ u16 to_f16(float f) {
    u16 h; asm("cvt.rn.f16.f32 %0, %1;" : "=h"(h) : "f"(f)); return h;
}
// packs (lo -> low half, hi -> high half)
__device__ __forceinline__ u32 pack_f16x2(float lo, float hi) {
    u32 r; asm("cvt.rn.f16x2.f32 %0, %1, %2;" : "=r"(r) : "f"(hi), "f"(lo)); return r;
}

// ---------- warp mma: D(16x8,f32) += A(16x16,f16 row) * B(16x8,f16 col) ----------
__device__ __forceinline__ void mma_f16(float* d, const u32* a, const u32* b) {
    asm volatile("mma.sync.aligned.m16n8k16.row.col.f32.f16.f16.f32 "
        "{%0,%1,%2,%3},{%4,%5,%6,%7},{%8,%9},{%0,%1,%2,%3};"
        : "+f"(d[0]), "+f"(d[1]), "+f"(d[2]), "+f"(d[3])
        : "r"(a[0]), "r"(a[1]), "r"(a[2]), "r"(a[3]), "r"(b[0]), "r"(b[1]));
}

// ======================= gate kernels =======================
__global__ void __launch_bounds__(320) gate_pool(const float* __restrict__ x) {
    int bc = blockIdx.x;
    const float4* p4 = (const float4*)(x + (size_t)bc * NPIX);
    float s = 0.f;
    #pragma unroll
    for (int k = 0; k < 5; k++) {             // 1600 float4 = 320 x 5 exactly
        float4 v = __ldg(p4 + k * 320 + threadIdx.x);
        s += (v.x + v.y) + (v.z + v.w);
    }
    __shared__ float red[10];
    #pragma unroll
    for (int o = 16; o; o >>= 1) s += __shfl_down_sync(0xffffffffu, s, o);
    if ((threadIdx.x & 31) == 0) red[threadIdx.x >> 5] = s;
    __syncthreads();
    if (threadIdx.x < 32) {
        float v = (threadIdx.x < 10) ? red[threadIdx.x] : 0.f;
        #pragma unroll
        for (int o = 8; o; o >>= 1) v += __shfl_down_sync(0xffffffffu, v, o);
        if (threadIdx.x == 0) g_pooled[bc] = v * (1.0f / (float)NPIX);
    }
}

__global__ void __launch_bounds__(256) gate_select(const float* __restrict__ Wg,
                                                   const float* __restrict__ bg) {
    int w = threadIdx.x >> 5, lane = threadIdx.x & 31;
    if (w >= BDIM) return;
    float best = -1e30f; int bi = 0;
    for (int e = 0; e < E_EXPERTS; e++) {
        float s = 0.f;
        for (int c = lane; c < CDIM; c += 32) s += g_pooled[w * CDIM + c] * Wg[e * CDIM + c];
        #pragma unroll
        for (int o = 16; o; o >>= 1) s += __shfl_down_sync(0xffffffffu, s, o);
        s += bg[e];
        s = __shfl_sync(0xffffffffu, s, 0);
        if (s > best) { best = s; bi = e; }
    }
    if (lane == 0) g_expert[w] = bi;
}

// ======================= smem layout (bytes) =======================
// Split-row fp16 layout: K=128 in 2 planes of 64 elems; row = 64 f16 = 128B
// padded to 144B (conflict-free fragment LDS: bank = 4*gr + q).
// DEDICATED buffers (no multiplexing -> 4 barriers/tile):
// XHI : 0       (2 branches x [2 planes x 64 px-rows x 144B] = 36864)
// DHI : 36864   (same shape, 36864)
// SDT : 73728   (fp32 [o*65+px], 33280)
// W   : 107008  (br*36864; 2 planes x 128 rows x 144B)
// W1  : 180736  (2 planes x 64 rows x 144B = 18432)
// sA  : 199168 (128 f32);  sS : 199680 (128 f32)
#define XHI_OFF  0
#define DHI_OFF  36864
#define SDT_OFF  73728
#define W_OFF    107008
#define W1_OFF   180736
#define SA_OFF   199168
#define SS_OFF   199680
#define SMEM_BYTES 200192

__global__ void __launch_bounds__(512, 1) moe_expert(
    const float* __restrict__ x,
    const float* __restrict__ Wrgb, const float* __restrict__ brgb,
    const float* __restrict__ Wtir, const float* __restrict__ btir,
    const float* __restrict__ Wt1,  const float* __restrict__ bt1,
    const float* __restrict__ Wt2,  const float* __restrict__ bt2,
    float* __restrict__ out)
{
    extern __shared__ char smc[];
    float* sA = (float*)(smc + SA_OFF);
    float* sS = (float*)(smc + SS_OFF);

    const int t    = threadIdx.x;
    const int w    = t >> 5;
    const int lane = t & 31;
    const int gr   = lane >> 2;
    const int q    = lane & 3;
    const int br   = w >> 3;            // branch: 0=RGB, 1=TIR
    const int msub = w & 7;
    const int rbase = msub * 16;        // GEMM1 o-rows

    const int b = blockIdx.y;
    const int e = g_expert[b];

    // 18 blocks/batch: 10x6 + 8x5 = 100 tiles of 64 px (144 blocks = 1 wave)
    const int ib    = blockIdx.x;
    const int tile0 = ib < 10 ? ib * 6 : 60 + (ib - 10) * 5;
    const int tcnt  = ib < 10 ? 6 : 5;

    // ---- hoisted per-thread constants ----
    const float bz0 = __ldg((br ? btir : brgb) + e * HALF + rbase + gr);
    const float bz1 = __ldg((br ? btir : brgb) + e * HALF + rbase + gr + 8);
    // GEMM2': pxt = px 16-tile (0..3), npair selects 4 n8 (m) tiles
    const int   pxt   = msub >> 1;
    const int   npair = msub & 1;
    float w2x[4], w2y[4], b1x[4], b1y[4];
    #pragma unroll
    for (int j = 0; j < 4; j++) {
        int m0 = (npair * 4 + j) * 8 + 2 * q;
        w2x[j] = __ldg(Wt2 + e * QUART + m0);
        w2y[j] = __ldg(Wt2 + e * QUART + m0 + 1);
        b1x[j] = __ldg(bt1 + e * QUART + m0);
        b1y[j] = __ldg(bt1 + e * QUART + m0 + 1);
    }
    const float bt2v = __ldg(bt2 + e);

    // ---------------- prologue: W, W1 -> fp16 in smem ----------------
    #pragma unroll
    for (int br2 = 0; br2 < 2; br2++) {
        const float* gW = (br2 ? Wtir : Wrgb) + (size_t)e * HALF * HALF;
        char* bh = smc + W_OFF + br2 * 36864;
        #pragma unroll 4
        for (int it = 0; it < 16; it++) {
            int lin = it * 512 + t;            // 8192 = 128 o x 64 c-pairs
            int o = lin >> 6, c0 = (lin & 63) * 2;
            float2 v = __ldg((const float2*)(gW + o * 128 + c0));
            int addr = (c0 >> 6) * 18432 + o * 144 + (c0 & 63) * 2;
            *(u32*)(bh + addr) = pack_f16x2(v.x, v.y);
        }
    }
    {
        const float* g1 = Wt1 + (size_t)e * QUART * HALF;
        char* bh = smc + W1_OFF;
        #pragma unroll 4
        for (int it = 0; it < 8; it++) {
            int lin = it * 512 + t;            // 4096 = 64 m x 64 c-pairs
            int m = lin >> 6, c0 = (lin & 63) * 2;
            float2 v = __ldg((const float2*)(g1 + m * 128 + c0));
            int addr = (c0 >> 6) * 9216 + m * 144 + (c0 & 63) * 2;
            *(u32*)(bh + addr) = pack_f16x2(v.x, v.y);
        }
    }

    // ---- Bx builder mapping: 128 channel-pairs x 4 px-quarters (16 px each) ----
    const int cp  = t & 127;                      // channel pair 0..127
    const int pxq = t >> 7;                       // px quarter 0..3
    const int c0b = 2 * cp;                       // channel base 0..254
    const int brx = c0b >> 7;                     // 0..1
    const int plx = (c0b & 64) ? 9216 : 0;
    const int cin = (c0b & 63) * 2;
    const float* gx0 = x + ((size_t)(b * CDIM + c0b)) * NPIX;

    for (int tt = 0; tt < tcnt; tt++) {
        const int pix0 = (tile0 + tt) * PIX;

        // ---- phase 1: build xhi fp16 tile from gmem ----
        {
            char* bh = smc + XHI_OFF + brx * 18432 + plx;
            const float* g = gx0 + pix0 + pxq * 16;
            #pragma unroll
            for (int ch = 0; ch < 2; ch++) {      // 2 chunks of 8 px
                float a0[8], a1[8];
                *(float4*)a0       = __ldg((const float4*)(g + ch * 8));
                *(float4*)(a0 + 4) = __ldg((const float4*)(g + ch * 8 + 4));
                *(float4*)a1       = __ldg((const float4*)(g + NPIX + ch * 8));
                *(float4*)(a1 + 4) = __ldg((const float4*)(g + NPIX + ch * 8 + 4));
                #pragma unroll
                for (int j = 0; j < 8; j++) {
                    int px = pxq * 16 + ch * 8 + j;
                    *(u32*)(bh + px * 144 + cin) = pack_f16x2(a0[j], a1[j]);
                }
            }
        }
        __syncthreads();   // B1: xhi ready (also covers prologue on tt=0)

        // ---- GEMM1: acc[8][4] = Whi@xhi over N=64 ----
        float acc[8][4];
        #pragma unroll
        for (int nt = 0; nt < 8; nt++)
            #pragma unroll
            for (int i = 0; i < 4; i++) acc[nt][i] = 0.f;
        {
            const char* Ah = smc + W_OFF + br * 36864;
            const char* Bh = smc + XHI_OFF + br * 18432;
            const int rb = (rbase + gr) * 144, rb8 = rb + 1152;
            #pragma unroll 2
            for (int kt = 0; kt < 8; kt++) {
                const int wp = (kt >> 2) * 18432 + (kt & 3) * 32 + q * 4;
                const int bp = (kt >> 2) * 9216  + (kt & 3) * 32 + q * 4;
                u32 ah[4];
                ah[0] = *(const u32*)(Ah + wp + rb);
                ah[1] = *(const u32*)(Ah + wp + rb8);
                ah[2] = *(const u32*)(Ah + wp + rb + 16);
                ah[3] = *(const u32*)(Ah + wp + rb8 + 16);
                #pragma unroll
                for (int nt = 0; nt < 8; nt++) {
                    int nb2 = (nt * 8 + gr) * 144;
                    u32 bh2[2];
                    bh2[0] = *(const u32*)(Bh + bp + nb2);
                    bh2[1] = *(const u32*)(Bh + bp + nb2 + 16);
                    mma_f16(acc[nt], ah, bh2);
                }
            }
        }
        // epilogue: + residual + bias (exact fp32, gmem L2-hot)
        {
            const float* gxr = x + ((size_t)(b * CDIM) + br * HALF) * NPIX + pix0;
            const float* r0p = gxr + (size_t)(rbase + gr) * NPIX;
            const float* r1p = gxr + (size_t)(rbase + gr + 8) * NPIX;
            #pragma unroll
            for (int nt = 0; nt < 8; nt++) {
                int c0 = nt * 8 + 2 * q;
                float2 x0 = __ldg((const float2*)(r0p + c0));
                float2 x1 = __ldg((const float2*)(r1p + c0));
                acc[nt][0] += x0.x + bz0;
                acc[nt][1] += x0.y + bz0;
                acc[nt][2] += x1.x + bz1;
                acc[nt][3] += x1.y + bz1;
            }
        }

        // ---- phase 2: Dhi store; TIR also stages raw D to sDt; RGB zeros sS ----
        {
            char* Dh = smc + DHI_OFF + br * 18432;
            const int pl0 = (rbase & 64) ? 9216 : 0;
            const int in0 = ((rbase + gr) & 63) * 2;
            #pragma unroll
            for (int nt = 0; nt < 8; nt++) {
                int px0 = nt * 8 + 2 * q;
                #pragma unroll
                for (int i = 0; i < 4; i++) {
                    int px = px0 + (i & 1);
                    int in = in0 + ((i < 2) ? 0 : 16);
                    *(u16*)(Dh + pl0 + px * 144 + in) = to_f16(acc[nt][i]);
                }
            }
            if (br == 1) {
                float* sDt = (float*)(smc + SDT_OFF);   // [o*65 + px]
                float* d0 = sDt + (rbase + gr) * 65;
                float* d1 = sDt + (rbase + gr + 8) * 65;
                #pragma unroll
                for (int nt = 0; nt < 8; nt++) {
                    int c0 = nt * 8 + 2 * q;
                    d0[c0]     = acc[nt][0];
                    d0[c0 + 1] = acc[nt][1];
                    d1[c0]     = acc[nt][2];
                    d1[c0 + 1] = acc[nt][3];
                }
            }
            if (t < 128) sS[t] = 0.f;
        }
        __syncthreads();   // B2: Dhi + sDt + sS-zero visible

        // ---- GEMM2': h^T = Dhi@W1hi^T ; fused attention reduction ----
        {
            float acc2[4][4];
            #pragma unroll
            for (int j = 0; j < 4; j++)
                #pragma unroll
                for (int i = 0; i < 4; i++) acc2[j][i] = 0.f;

            const char* A2 = smc + DHI_OFF + br * 18432;   // Dhi (px rows)
            const char* B2h = smc + W1_OFF;                // W1 hi (m rows)
            const int prb = (pxt * 16 + gr) * 144, prb8 = prb + 1152;
            #pragma unroll 2
            for (int kt = 0; kt < 8; kt++) {
                const int wpA = (kt >> 2) * 9216 + (kt & 3) * 32 + q * 4;
                const int wpB = (kt >> 2) * 9216 + (kt & 3) * 32 + q * 4;
                u32 ah[4];
                ah[0] = *(const u32*)(A2 + wpA + prb);
                ah[1] = *(const u32*)(A2 + wpA + prb8);
                ah[2] = *(const u32*)(A2 + wpA + prb + 16);
                ah[3] = *(const u32*)(A2 + wpA + prb8 + 16);
                #pragma unroll
                for (int j = 0; j < 4; j++) {
                    int nb2 = ((npair * 4 + j) * 8 + gr) * 144;
                    u32 bh2[2];
                    bh2[0] = *(const u32*)(B2h + wpB + nb2);
                    bh2[1] = *(const u32*)(B2h + wpB + nb2 + 16);
                    mma_f16(acc2[j], ah, bh2);
                }
            }
            // fused attention partials: s[px] += w2[m]*relu(h + bt1)
            float p0 = 0.f, p8 = 0.f;
            #pragma unroll
            for (int j = 0; j < 4; j++) {
                p0 += w2x[j] * fmaxf(acc2[j][0] + b1x[j], 0.f)
                    + w2y[j] * fmaxf(acc2[j][1] + b1y[j], 0.f);
                p8 += w2x[j] * fmaxf(acc2[j][2] + b1x[j], 0.f)
                    + w2y[j] * fmaxf(acc2[j][3] + b1y[j], 0.f);
            }
            p0 += __shfl_xor_sync(0xffffffffu, p0, 1);
            p0 += __shfl_xor_sync(0xffffffffu, p0, 2);
            p8 += __shfl_xor_sync(0xffffffffu, p8, 1);
            p8 += __shfl_xor_sync(0xffffffffu, p8, 2);
            if (q == 0) {
                atomicAdd(&sS[br * 64 + pxt * 16 + gr], p0);
                atomicAdd(&sS[br * 64 + pxt * 16 + gr + 8], p8);
            }
        }
        __syncthreads();   // B3: sS complete

        // ---- sigmoid ----
        if (t < 128) sA[t] = 1.f / (1.f + expf(-(sS[t] + bt2v)));
        __syncthreads();   // B4: sA ready

        // ---- fuse + store (RGB warps): out = aR*Dr + aT*Dt ----
        if (br == 0) {
            const float* sDt = (const float*)(smc + SDT_OFF);
            const float* d0 = sDt + (rbase + gr) * 65;
            const float* d1 = sDt + (rbase + gr + 8) * 65;
            float* go = out + (size_t)(b * HALF) * NPIX + pix0;
            float* g0 = go + (size_t)(rbase + gr) * NPIX;
            float* g1 = go + (size_t)(rbase + gr + 8) * NPIX;
            #pragma unroll
            for (int nt = 0; nt < 8; nt++) {
                int c0 = nt * 8 + 2 * q;
                float aR0 = sA[c0], aR1 = sA[c0 + 1];
                float aT0 = sA[64 + c0], aT1 = sA[64 + c0 + 1];
                float2 v0, v1;
                v0.x = aR0 * acc[nt][0] + aT0 * d0[c0];
                v0.y = aR1 * acc[nt][1] + aT1 * d0[c0 + 1];
                v1.x = aR0 * acc[nt][2] + aT0 * d1[c0];
                v1.y = aR1 * acc[nt][3] + aT1 * d1[c0 + 1];
                *(float2*)(g0 + c0) = v0;
                *(float2*)(g1 + c0) = v1;
            }
        }
        // next tile's B1 protects xhi/sDt/sA reuse
    }
}

extern "C" void kernel_launch(void* const* d_in, const int* in_sizes, int n_in,
                              void* d_out, int out_size) {
    const float* x    = (const float*)d_in[0];
    const float* Wg   = (const float*)d_in[1];
    const float* bg   = (const float*)d_in[2];
    const float* Wrgb = (const float*)d_in[3];
    const float* brgb = (const float*)d_in[4];
    const float* Wtir = (const float*)d_in[5];
    const float* btir = (const float*)d_in[6];
    const float* Wt1  = (const float*)d_in[7];
    const float* bt1  = (const float*)d_in[8];
    const float* Wt2  = (const float*)d_in[9];
    const float* bt2  = (const float*)d_in[10];
    float* out = (float*)d_out;

    gate_pool<<<BDIM * CDIM, 320>>>(x);
    gate_select<<<1, 256>>>(Wg, bg);

    cudaFuncSetAttribute(moe_expert, cudaFuncAttributeMaxDynamicSharedMemorySize, SMEM_BYTES);
    dim3 grid(18, BDIM);
    moe_expert<<<grid, 512, SMEM_BYTES>>>(x, Wrgb, brgb, Wtir, btir,
                                          Wt1, bt1, Wt2, bt2, out);
}

// round 12
// speedup vs baseline: 1.1265x; 1.1265x over previous
#include <cuda_runtime.h>
#include <cstdint>
#include <math.h>

#define E_EXPERTS 5
#define CDIM      256
#define HALF      128
#define QUART     64
#define BDIM      8
#define NPIX      6400
#define PIX       64

typedef uint32_t u32;
typedef uint16_t u16;

__device__ float g_pooled[BDIM * CDIM];

// ---------- fp16 helpers ----------
__device__ __forceinline__ u16 to_f16(float f) {
    u16 h; asm("cvt.rn.f16.f32 %0, %1;" : "=h"(h) : "f"(f)); return h;
}
// packs (lo -> low half, hi -> high half)
__device__ __forceinline__ u32 pack_f16x2(float lo, float hi) {
    u32 r; asm("cvt.rn.f16x2.f32 %0, %1, %2;" : "=r"(r) : "f"(hi), "f"(lo)); return r;
}

// ---------- warp mma: D(16x8,f32) += A(16x16,f16 row) * B(16x8,f16 col) ----------
__device__ __forceinline__ void mma_f16(float* d, const u32* a, const u32* b) {
    asm volatile("mma.sync.aligned.m16n8k16.row.col.f32.f16.f16.f32 "
        "{%0,%1,%2,%3},{%4,%5,%6,%7},{%8,%9},{%0,%1,%2,%3};"
        : "+f"(d[0]), "+f"(d[1]), "+f"(d[2]), "+f"(d[3])
        : "r"(a[0]), "r"(a[1]), "r"(a[2]), "r"(a[3]), "r"(b[0]), "r"(b[1]));
}

// ======================= gate kernel 1 (pool) =======================
__global__ void __launch_bounds__(320) gate_pool(const float* __restrict__ x) {
    int bc = blockIdx.x;
    const float4* p4 = (const float4*)(x + (size_t)bc * NPIX);
    float s = 0.f;
    #pragma unroll
    for (int k = 0; k < 5; k++) {             // 1600 float4 = 320 x 5 exactly
        float4 v = __ldg(p4 + k * 320 + threadIdx.x);
        s += (v.x + v.y) + (v.z + v.w);
    }
    __shared__ float red[10];
    #pragma unroll
    for (int o = 16; o; o >>= 1) s += __shfl_down_sync(0xffffffffu, s, o);
    if ((threadIdx.x & 31) == 0) red[threadIdx.x >> 5] = s;
    __syncthreads();
    if (threadIdx.x < 32) {
        float v = (threadIdx.x < 10) ? red[threadIdx.x] : 0.f;
        #pragma unroll
        for (int o = 8; o; o >>= 1) v += __shfl_down_sync(0xffffffffu, v, o);
        if (threadIdx.x == 0) g_pooled[bc] = v * (1.0f / (float)NPIX);
    }
}

// ======================= smem layout (bytes) =======================
// Split-row fp16 layout: K=128 in 2 planes of 64 elems; row = 64 f16 = 128B
// padded to 144B (conflict-free fragment LDS: bank = 4*gr + q).
// Region A (36864B), time-multiplexed per tile:
//   phase 1: xhi(br) = br*18432 (2 planes x 64 px-rows x 144B)
//   phase 2: Dhi (same addressing)
//   phase 3: sDt fp32 [o*65+px] (33280B)
// W  : W_OFF + br*36864  (2 planes x 128 rows x 144B)
// W1 : W1_OFF            (2 planes x 64 rows x 144B)
// sA : 128 f32 @ SA_OFF;  sS : 128 f32 @ SS_OFF (also gate logits at start)
#define W_OFF    36864
#define W1_OFF   110592
#define SA_OFF   129024
#define SS_OFF   129536
#define SMEM_BYTES 130048

__global__ void __launch_bounds__(512, 1) moe_expert(
    const float* __restrict__ x,
    const float* __restrict__ Wg,   const float* __restrict__ bg,
    const float* __restrict__ Wrgb, const float* __restrict__ brgb,
    const float* __restrict__ Wtir, const float* __restrict__ btir,
    const float* __restrict__ Wt1,  const float* __restrict__ bt1,
    const float* __restrict__ Wt2,  const float* __restrict__ bt2,
    float* __restrict__ out)
{
    extern __shared__ char smc[];
    float* sA = (float*)(smc + SA_OFF);
    float* sS = (float*)(smc + SS_OFF);

    const int t    = threadIdx.x;
    const int w    = t >> 5;
    const int lane = t & 31;
    const int gr   = lane >> 2;
    const int q    = lane & 3;
    const int br   = w >> 3;            // branch: 0=RGB, 1=TIR
    const int msub = w & 7;
    const int rbase = msub * 16;        // GEMM1 o-rows

    const int b = blockIdx.y;

    // ---- inline gate: warp e computes logit e; argmax (strict >, first max) ----
    {
        if (w < E_EXPERTS) {
            const float* pw = Wg + w * CDIM;
            const float* pp = g_pooled + b * CDIM;
            float s = 0.f;
            #pragma unroll
            for (int c = lane; c < CDIM; c += 32) s += pp[c] * pw[c];
            #pragma unroll
            for (int o = 16; o; o >>= 1) s += __shfl_down_sync(0xffffffffu, s, o);
            if (lane == 0) sS[w] = s + __ldg(bg + w);
        }
    }
    __syncthreads();
    int e = 0;
    {
        float best = sS[0];
        #pragma unroll
        for (int i = 1; i < E_EXPERTS; i++) {
            float v = sS[i];
            if (v > best) { best = v; e = i; }
        }
    }

    // 18 blocks/batch: 10x6 + 8x5 = 100 tiles of 64 px (144 blocks = 1 wave)
    const int ib    = blockIdx.x;
    const int tile0 = ib < 10 ? ib * 6 : 60 + (ib - 10) * 5;
    const int tcnt  = ib < 10 ? 6 : 5;

    // ---- hoisted per-thread constants ----
    const float bz0 = __ldg((br ? btir : brgb) + e * HALF + rbase + gr);
    const float bz1 = __ldg((br ? btir : brgb) + e * HALF + rbase + gr + 8);
    // GEMM2': pxt = px 16-tile (0..3), npair selects 4 n8 (m) tiles
    const int   pxt   = msub >> 1;
    const int   npair = msub & 1;
    float w2x[4], w2y[4], b1x[4], b1y[4];
    #pragma unroll
    for (int j = 0; j < 4; j++) {
        int m0 = (npair * 4 + j) * 8 + 2 * q;
        w2x[j] = __ldg(Wt2 + e * QUART + m0);
        w2y[j] = __ldg(Wt2 + e * QUART + m0 + 1);
        b1x[j] = __ldg(bt1 + e * QUART + m0);
        b1y[j] = __ldg(bt1 + e * QUART + m0 + 1);
    }
    const float bt2v = __ldg(bt2 + e);

    // ---------------- prologue: W, W1 -> fp16 in smem ----------------
    #pragma unroll
    for (int br2 = 0; br2 < 2; br2++) {
        const float* gW = (br2 ? Wtir : Wrgb) + (size_t)e * HALF * HALF;
        char* bh = smc + W_OFF + br2 * 36864;
        #pragma unroll 4
        for (int it = 0; it < 16; it++) {
            int lin = it * 512 + t;            // 8192 = 128 o x 64 c-pairs
            int o = lin >> 6, c0 = (lin & 63) * 2;
            float2 v = __ldg((const float2*)(gW + o * 128 + c0));
            int addr = (c0 >> 6) * 18432 + o * 144 + (c0 & 63) * 2;
            *(u32*)(bh + addr) = pack_f16x2(v.x, v.y);
        }
    }
    {
        const float* g1 = Wt1 + (size_t)e * QUART * HALF;
        char* bh = smc + W1_OFF;
        #pragma unroll 4
        for (int it = 0; it < 8; it++) {
            int lin = it * 512 + t;            // 4096 = 64 m x 64 c-pairs
            int m = lin >> 6, c0 = (lin & 63) * 2;
            float2 v = __ldg((const float2*)(g1 + m * 128 + c0));
            int addr = (c0 >> 6) * 9216 + m * 144 + (c0 & 63) * 2;
            *(u32*)(bh + addr) = pack_f16x2(v.x, v.y);
        }
    }

    // ---- Bx builder mapping: 128 channel-pairs x 4 px-quarters (16 px each) ----
    const int cp  = t & 127;                      // channel pair 0..127
    const int pxq = t >> 7;                       // px quarter 0..3
    const int c0b = 2 * cp;                       // channel base 0..254
    const int brx = c0b >> 7;                     // 0..1
    const int plx = (c0b & 64) ? 9216 : 0;
    const int cin = (c0b & 63) * 2;
    const float* gx0 = x + ((size_t)(b * CDIM + c0b)) * NPIX;

    for (int tt = 0; tt < tcnt; tt++) {
        const int pix0 = (tile0 + tt) * PIX;
        __syncthreads();   // region A free (covers prologue + gate on tt=0)

        // ---- build xhi fp16 tile from gmem (L2-hot after gate_pool) ----
        {
            char* bh = smc + brx * 18432 + plx;
            const float* g = gx0 + pix0 + pxq * 16;
            #pragma unroll
            for (int ch = 0; ch < 2; ch++) {      // 2 chunks of 8 px
                float a0[8], a1[8];
                *(float4*)a0       = __ldg((const float4*)(g + ch * 8));
                *(float4*)(a0 + 4) = __ldg((const float4*)(g + ch * 8 + 4));
                *(float4*)a1       = __ldg((const float4*)(g + NPIX + ch * 8));
                *(float4*)(a1 + 4) = __ldg((const float4*)(g + NPIX + ch * 8 + 4));
                #pragma unroll
                for (int j = 0; j < 8; j++) {
                    int px = pxq * 16 + ch * 8 + j;
                    *(u32*)(bh + px * 144 + cin) = pack_f16x2(a0[j], a1[j]);
                }
            }
        }
        __syncthreads();

        // ---- GEMM1: acc[8][4] = Whi@xhi over N=64 ----
        float acc[8][4];
        #pragma unroll
        for (int nt = 0; nt < 8; nt++)
            #pragma unroll
            for (int i = 0; i < 4; i++) acc[nt][i] = 0.f;
        {
            const char* Ah = smc + W_OFF + br * 36864;
            const char* Bh = smc + br * 18432;
            const int rb = (rbase + gr) * 144, rb8 = rb + 1152;
            #pragma unroll 2
            for (int kt = 0; kt < 8; kt++) {
                const int wp = (kt >> 2) * 18432 + (kt & 3) * 32 + q * 4;
                const int bp = (kt >> 2) * 9216  + (kt & 3) * 32 + q * 4;
                u32 ah[4];
                ah[0] = *(const u32*)(Ah + wp + rb);
                ah[1] = *(const u32*)(Ah + wp + rb8);
                ah[2] = *(const u32*)(Ah + wp + rb + 16);
                ah[3] = *(const u32*)(Ah + wp + rb8 + 16);
                #pragma unroll
                for (int nt = 0; nt < 8; nt++) {
                    int nb2 = (nt * 8 + gr) * 144;
                    u32 bh2[2];
                    bh2[0] = *(const u32*)(Bh + bp + nb2);
                    bh2[1] = *(const u32*)(Bh + bp + nb2 + 16);
                    mma_f16(acc[nt], ah, bh2);
                }
            }
        }
        // epilogue: + residual + bias (exact fp32, gmem L1/L2-hot)
        {
            const float* gxr = x + ((size_t)(b * CDIM) + br * HALF) * NPIX + pix0;
            const float* r0p = gxr + (size_t)(rbase + gr) * NPIX;
            const float* r1p = gxr + (size_t)(rbase + gr + 8) * NPIX;
            #pragma unroll
            for (int nt = 0; nt < 8; nt++) {
                int c0 = nt * 8 + 2 * q;
                float2 x0 = __ldg((const float2*)(r0p + c0));
                float2 x1 = __ldg((const float2*)(r1p + c0));
                acc[nt][0] += x0.x + bz0;
                acc[nt][1] += x0.y + bz0;
                acc[nt][2] += x1.x + bz1;
                acc[nt][3] += x1.y + bz1;
            }
        }
        __syncthreads();   // xhi reads done

        // ---- store Dhi fp16 (overwrites xhi); zero sS ----
        {
            char* Dh = smc + br * 18432;
            const int pl0 = (rbase & 64) ? 9216 : 0;
            const int in0 = ((rbase + gr) & 63) * 2;
            #pragma unroll
            for (int nt = 0; nt < 8; nt++) {
                int px0 = nt * 8 + 2 * q;
                #pragma unroll
                for (int i = 0; i < 4; i++) {
                    int px = px0 + (i & 1);
                    int in = in0 + ((i < 2) ? 0 : 16);
                    *(u16*)(Dh + pl0 + px * 144 + in) = to_f16(acc[nt][i]);
                }
            }
            if (t < 128) sS[t] = 0.f;
        }
        __syncthreads();

        // ---- GEMM2': h^T = Dhi@W1hi^T ; fused attention reduction ----
        {
            float acc2[4][4];
            #pragma unroll
            for (int j = 0; j < 4; j++)
                #pragma unroll
                for (int i = 0; i < 4; i++) acc2[j][i] = 0.f;

            const char* A2 = smc + br * 18432;         // Dhi (px rows)
            const char* B2h = smc + W1_OFF;            // W1 hi (m rows)
            const int prb = (pxt * 16 + gr) * 144, prb8 = prb + 1152;
            #pragma unroll 2
            for (int kt = 0; kt < 8; kt++) {
                const int wpA = (kt >> 2) * 9216 + (kt & 3) * 32 + q * 4;
                const int wpB = (kt >> 2) * 9216 + (kt & 3) * 32 + q * 4;
                u32 ah[4];
                ah[0] = *(const u32*)(A2 + wpA + prb);
                ah[1] = *(const u32*)(A2 + wpA + prb8);
                ah[2] = *(const u32*)(A2 + wpA + prb + 16);
                ah[3] = *(const u32*)(A2 + wpA + prb8 + 16);
                #pragma unroll
                for (int j = 0; j < 4; j++) {
                    int nb2 = ((npair * 4 + j) * 8 + gr) * 144;
                    u32 bh2[2];
                    bh2[0] = *(const u32*)(B2h + wpB + nb2);
                    bh2[1] = *(const u32*)(B2h + wpB + nb2 + 16);
                    mma_f16(acc2[j], ah, bh2);
                }
            }
            // fused attention partials: s[px] += w2[m]*relu(h + bt1)
            float p0 = 0.f, p8 = 0.f;
            #pragma unroll
            for (int j = 0; j < 4; j++) {
                p0 += w2x[j] * fmaxf(acc2[j][0] + b1x[j], 0.f)
                    + w2y[j] * fmaxf(acc2[j][1] + b1y[j], 0.f);
                p8 += w2x[j] * fmaxf(acc2[j][2] + b1x[j], 0.f)
                    + w2y[j] * fmaxf(acc2[j][3] + b1y[j], 0.f);
            }
            p0 += __shfl_xor_sync(0xffffffffu, p0, 1);
            p0 += __shfl_xor_sync(0xffffffffu, p0, 2);
            p8 += __shfl_xor_sync(0xffffffffu, p8, 1);
            p8 += __shfl_xor_sync(0xffffffffu, p8, 2);
            if (q == 0) {
                atomicAdd(&sS[br * 64 + pxt * 16 + gr], p0);
                atomicAdd(&sS[br * 64 + pxt * 16 + gr + 8], p8);
            }
        }
        __syncthreads();   // D reads + sS done

        // ---- sigmoid + TIR stages raw D into sDt ----
        {
            if (t < 128) sA[t] = 1.f / (1.f + __expf(-(sS[t] + bt2v)));
            if (br == 1) {
                float* sDt = (float*)smc;           // [o*65 + px]
                float* d0 = sDt + (rbase + gr) * 65;
                float* d1 = sDt + (rbase + gr + 8) * 65;
                #pragma unroll
                for (int nt = 0; nt < 8; nt++) {
                    int c0 = nt * 8 + 2 * q;
                    d0[c0]     = acc[nt][0];
                    d0[c0 + 1] = acc[nt][1];
                    d1[c0]     = acc[nt][2];
                    d1[c0 + 1] = acc[nt][3];
                }
            }
        }
        __syncthreads();

        // ---- fuse + store (RGB warps): out = aR*Dr + aT*Dt ----
        if (br == 0) {
            const float* sDt = (const float*)smc;
            const float* d0 = sDt + (rbase + gr) * 65;
            const float* d1 = sDt + (rbase + gr + 8) * 65;
            float* go = out + (size_t)(b * HALF) * NPIX + pix0;
            float* g0 = go + (size_t)(rbase + gr) * NPIX;
            float* g1 = go + (size_t)(rbase + gr + 8) * NPIX;
            #pragma unroll
            for (int nt = 0; nt < 8; nt++) {
                int c0 = nt * 8 + 2 * q;
                float aR0 = sA[c0], aR1 = sA[c0 + 1];
                float aT0 = sA[64 + c0], aT1 = sA[64 + c0 + 1];
                float2 v0, v1;
                v0.x = aR0 * acc[nt][0] + aT0 * d0[c0];
                v0.y = aR1 * acc[nt][1] + aT1 * d0[c0 + 1];
                v1.x = aR0 * acc[nt][2] + aT0 * d1[c0];
                v1.y = aR1 * acc[nt][3] + aT1 * d1[c0 + 1];
                *(float2*)(g0 + c0) = v0;
                *(float2*)(g1 + c0) = v1;
            }
        }
    }
}

extern "C" void kernel_launch(void* const* d_in, const int* in_sizes, int n_in,
                              void* d_out, int out_size) {
    const float* x    = (const float*)d_in[0];
    const float* Wg   = (const float*)d_in[1];
    const float* bg   = (const float*)d_in[2];
    const float* Wrgb = (const float*)d_in[3];
    const float* brgb = (const float*)d_in[4];
    const float* Wtir = (const float*)d_in[5];
    const float* btir = (const float*)d_in[6];
    const float* Wt1  = (const float*)d_in[7];
    const float* bt1  = (const float*)d_in[8];
    const float* Wt2  = (const float*)d_in[9];
    const float* bt2  = (const float*)d_in[10];
    float* out = (float*)d_out;

    gate_pool<<<BDIM * CDIM, 320>>>(x);

    cudaFuncSetAttribute(moe_expert, cudaFuncAttributeMaxDynamicSharedMemorySize, SMEM_BYTES);
    dim3 grid(18, BDIM);
    moe_expert<<<grid, 512, SMEM_BYTES>>>(x, Wg, bg, Wrgb, brgb, Wtir, btir,
                                          Wt1, bt1, Wt2, bt2, out);
}

// round 13
// speedup vs baseline: 1.4798x; 1.3137x over previous
#include <cuda_runtime.h>
#include <cstdint>
#include <math.h>

#define E_EXPERTS 5
#define CDIM      256
#define HALF      128
#define QUART     64
#define BDIM      8
#define NPIX      6400
#define PIX       64

typedef uint32_t u32;
typedef uint16_t u16;

__device__ float g_pooled[BDIM * CDIM];

// ---------- fp16 helpers ----------
__device__ __forceinline__ u16 to_f16(float f) {
    u16 h; asm("cvt.rn.f16.f32 %0, %1;" : "=h"(h) : "f"(f)); return h;
}
// packs (lo -> low half, hi -> high half)
__device__ __forceinline__ u32 pack_f16x2(float lo, float hi) {
    u32 r; asm("cvt.rn.f16x2.f32 %0, %1, %2;" : "=r"(r) : "f"(hi), "f"(lo)); return r;
}

// ---------- warp mma: D(16x8,f32) += A(16x16,f16 row) * B(16x8,f16 col) ----------
__device__ __forceinline__ void mma_f16(float* d, const u32* a, const u32* b) {
    asm volatile("mma.sync.aligned.m16n8k16.row.col.f32.f16.f16.f32 "
        "{%0,%1,%2,%3},{%4,%5,%6,%7},{%8,%9},{%0,%1,%2,%3};"
        : "+f"(d[0]), "+f"(d[1]), "+f"(d[2]), "+f"(d[3])
        : "r"(a[0]), "r"(a[1]), "r"(a[2]), "r"(a[3]), "r"(b[0]), "r"(b[1]));
}

// ======================= gate kernel 1 (pool) =======================
__global__ void __launch_bounds__(320) gate_pool(const float* __restrict__ x) {
    int bc = blockIdx.x;
    const float4* p4 = (const float4*)(x + (size_t)bc * NPIX);
    float s = 0.f;
    #pragma unroll
    for (int k = 0; k < 5; k++) {             // 1600 float4 = 320 x 5 exactly
        float4 v = __ldg(p4 + k * 320 + threadIdx.x);
        s += (v.x + v.y) + (v.z + v.w);
    }
    __shared__ float red[10];
    #pragma unroll
    for (int o = 16; o; o >>= 1) s += __shfl_down_sync(0xffffffffu, s, o);
    if ((threadIdx.x & 31) == 0) red[threadIdx.x >> 5] = s;
    __syncthreads();
    if (threadIdx.x < 32) {
        float v = (threadIdx.x < 10) ? red[threadIdx.x] : 0.f;
        #pragma unroll
        for (int o = 8; o; o >>= 1) v += __shfl_down_sync(0xffffffffu, v, o);
        if (threadIdx.x == 0) g_pooled[bc] = v * (1.0f / (float)NPIX);
    }
}

// ======================= smem layout (bytes) =======================
// Split-row fp16 layout: K=128 in 2 planes of 64 elems; row = 64 f16 = 128B
// padded to 144B (conflict-free fragment LDS: bank = 4*gr + q).
// Region A (36864B), time-multiplexed per tile:
//   phase 1: xhi(br) = br*18432 (2 planes x 64 px-rows x 144B)
//   phase 2: Dhi (same addressing)
//   phase 3: sDt fp32 [o*65+px] (33280B)
// W  : W_OFF + br*36864  (W' = W + I, 2 planes x 128 rows x 144B)
// W1 : W1_OFF            (2 planes x 64 rows x 144B)
// sA : 128 f32 @ SA_OFF;  sS : 128 f32 @ SS_OFF (also gate logits at start)
#define W_OFF    36864
#define W1_OFF   110592
#define SA_OFF   129024
#define SS_OFF   129536
#define SMEM_BYTES 130048

__global__ void __launch_bounds__(512, 1) moe_expert(
    const float* __restrict__ x,
    const float* __restrict__ Wg,   const float* __restrict__ bg,
    const float* __restrict__ Wrgb, const float* __restrict__ brgb,
    const float* __restrict__ Wtir, const float* __restrict__ btir,
    const float* __restrict__ Wt1,  const float* __restrict__ bt1,
    const float* __restrict__ Wt2,  const float* __restrict__ bt2,
    float* __restrict__ out)
{
    extern __shared__ char smc[];
    float* sA = (float*)(smc + SA_OFF);
    float* sS = (float*)(smc + SS_OFF);

    const int t    = threadIdx.x;
    const int w    = t >> 5;
    const int lane = t & 31;
    const int gr   = lane >> 2;
    const int q    = lane & 3;
    const int br   = w >> 3;            // branch: 0=RGB, 1=TIR
    const int msub = w & 7;
    const int rbase = msub * 16;        // GEMM1 o-rows

    const int b = blockIdx.y;

    // ---- inline gate: warp e computes logit e; argmax (strict >, first max) ----
    {
        if (w < E_EXPERTS) {
            const float* pw = Wg + w * CDIM;
            const float* pp = g_pooled + b * CDIM;
            float s = 0.f;
            #pragma unroll
            for (int c = lane; c < CDIM; c += 32) s += pp[c] * pw[c];
            #pragma unroll
            for (int o = 16; o; o >>= 1) s += __shfl_down_sync(0xffffffffu, s, o);
            if (lane == 0) sS[w] = s + __ldg(bg + w);
        }
    }
    __syncthreads();
    int e = 0;
    {
        float best = sS[0];
        #pragma unroll
        for (int i = 1; i < E_EXPERTS; i++) {
            float v = sS[i];
            if (v > best) { best = v; e = i; }
        }
    }

    // 18 blocks/batch: 10x6 + 8x5 = 100 tiles of 64 px (144 blocks = 1 wave)
    const int ib    = blockIdx.x;
    const int tile0 = ib < 10 ? ib * 6 : 60 + (ib - 10) * 5;
    const int tcnt  = ib < 10 ? 6 : 5;

    // ---- hoisted per-thread constants ----
    const float bz0 = __ldg((br ? btir : brgb) + e * HALF + rbase + gr);
    const float bz1 = __ldg((br ? btir : brgb) + e * HALF + rbase + gr + 8);
    // GEMM2': pxt = px 16-tile (0..3), npair selects 4 n8 (m) tiles
    const int   pxt   = msub >> 1;
    const int   npair = msub & 1;
    float w2x[4], w2y[4], b1x[4], b1y[4];
    #pragma unroll
    for (int j = 0; j < 4; j++) {
        int m0 = (npair * 4 + j) * 8 + 2 * q;
        w2x[j] = __ldg(Wt2 + e * QUART + m0);
        w2y[j] = __ldg(Wt2 + e * QUART + m0 + 1);
        b1x[j] = __ldg(bt1 + e * QUART + m0);
        b1y[j] = __ldg(bt1 + e * QUART + m0 + 1);
    }
    const float bt2v = __ldg(bt2 + e);

    // ------------ prologue: W' = W + I, W1 -> fp16 in smem ------------
    #pragma unroll
    for (int br2 = 0; br2 < 2; br2++) {
        const float* gW = (br2 ? Wtir : Wrgb) + (size_t)e * HALF * HALF;
        char* bh = smc + W_OFF + br2 * 36864;
        #pragma unroll 4
        for (int it = 0; it < 16; it++) {
            int lin = it * 512 + t;            // 8192 = 128 o x 64 c-pairs
            int o = lin >> 6, c0 = (lin & 63) * 2;
            float2 v = __ldg((const float2*)(gW + o * 128 + c0));
            float vx = v.x + ((o == c0)     ? 1.f : 0.f);   // residual fold
            float vy = v.y + ((o == c0 + 1) ? 1.f : 0.f);
            int addr = (c0 >> 6) * 18432 + o * 144 + (c0 & 63) * 2;
            *(u32*)(bh + addr) = pack_f16x2(vx, vy);
        }
    }
    {
        const float* g1 = Wt1 + (size_t)e * QUART * HALF;
        char* bh = smc + W1_OFF;
        #pragma unroll 4
        for (int it = 0; it < 8; it++) {
            int lin = it * 512 + t;            // 4096 = 64 m x 64 c-pairs
            int m = lin >> 6, c0 = (lin & 63) * 2;
            float2 v = __ldg((const float2*)(g1 + m * 128 + c0));
            int addr = (c0 >> 6) * 9216 + m * 144 + (c0 & 63) * 2;
            *(u32*)(bh + addr) = pack_f16x2(v.x, v.y);
        }
    }

    // ---- Bx builder: coalesced. thread = (cp8 = t>>3, sub = t&7);
    //      iteration it = branch; lanes contiguous along px within a row ----
    const int cp8 = t >> 3;                       // 0..63
    const int sub = t & 7;

    for (int tt = 0; tt < tcnt; tt++) {
        const int pix0 = (tile0 + tt) * PIX;
        __syncthreads();   // region A free (covers prologue + gate on tt=0)

        // ---- build xhi fp16 tile from gmem (coalesced: 4 lines/LDG) ----
        #pragma unroll
        for (int it = 0; it < 2; it++) {
            const int cpv = cp8 + it * 64;                 // channel pair
            const int c0b = 2 * cpv;
            char* bh = smc + it * 18432 + ((c0b & 64) ? 9216 : 0);
            const int cin = (c0b & 63) * 2;
            const float* g0 = x + ((size_t)(b * CDIM + c0b)) * NPIX + pix0;
            #pragma unroll
            for (int j = 0; j < 2; j++) {
                float4 a0 = __ldg((const float4*)(g0 + sub * 4 + j * 32));
                float4 a1 = __ldg((const float4*)(g0 + NPIX + sub * 4 + j * 32));
                int px0 = sub * 4 + j * 32;
                *(u32*)(bh + (px0    ) * 144 + cin) = pack_f16x2(a0.x, a1.x);
                *(u32*)(bh + (px0 + 1) * 144 + cin) = pack_f16x2(a0.y, a1.y);
                *(u32*)(bh + (px0 + 2) * 144 + cin) = pack_f16x2(a0.z, a1.z);
                *(u32*)(bh + (px0 + 3) * 144 + cin) = pack_f16x2(a0.w, a1.w);
            }
        }
        __syncthreads();

        // ---- GEMM1: acc[8][4] = W'hi@xhi over N=64 (residual inside W') ----
        float acc[8][4];
        #pragma unroll
        for (int nt = 0; nt < 8; nt++)
            #pragma unroll
            for (int i = 0; i < 4; i++) acc[nt][i] = 0.f;
        {
            const char* Ah = smc + W_OFF + br * 36864;
            const char* Bh = smc + br * 18432;
            const int rb = (rbase + gr) * 144, rb8 = rb + 1152;
            #pragma unroll 2
            for (int kt = 0; kt < 8; kt++) {
                const int wp = (kt >> 2) * 18432 + (kt & 3) * 32 + q * 4;
                const int bp = (kt >> 2) * 9216  + (kt & 3) * 32 + q * 4;
                u32 ah[4];
                ah[0] = *(const u32*)(Ah + wp + rb);
                ah[1] = *(const u32*)(Ah + wp + rb8);
                ah[2] = *(const u32*)(Ah + wp + rb + 16);
                ah[3] = *(const u32*)(Ah + wp + rb8 + 16);
                #pragma unroll
                for (int nt = 0; nt < 8; nt++) {
                    int nb2 = (nt * 8 + gr) * 144;
                    u32 bh2[2];
                    bh2[0] = *(const u32*)(Bh + bp + nb2);
                    bh2[1] = *(const u32*)(Bh + bp + nb2 + 16);
                    mma_f16(acc[nt], ah, bh2);
                }
            }
        }
        // epilogue: + bias only (residual already in W')
        #pragma unroll
        for (int nt = 0; nt < 8; nt++) {
            acc[nt][0] += bz0;
            acc[nt][1] += bz0;
            acc[nt][2] += bz1;
            acc[nt][3] += bz1;
        }
        __syncthreads();   // xhi reads done

        // ---- store Dhi fp16 (overwrites xhi); zero sS ----
        {
            char* Dh = smc + br * 18432;
            const int pl0 = (rbase & 64) ? 9216 : 0;
            const int in0 = ((rbase + gr) & 63) * 2;
            #pragma unroll
            for (int nt = 0; nt < 8; nt++) {
                int px0 = nt * 8 + 2 * q;
                #pragma unroll
                for (int i = 0; i < 4; i++) {
                    int px = px0 + (i & 1);
                    int in = in0 + ((i < 2) ? 0 : 16);
                    *(u16*)(Dh + pl0 + px * 144 + in) = to_f16(acc[nt][i]);
                }
            }
            if (t < 128) sS[t] = 0.f;
        }
        __syncthreads();

        // ---- GEMM2': h^T = Dhi@W1hi^T ; fused attention reduction ----
        {
            float acc2[4][4];
            #pragma unroll
            for (int j = 0; j < 4; j++)
                #pragma unroll
                for (int i = 0; i < 4; i++) acc2[j][i] = 0.f;

            const char* A2 = smc + br * 18432;         // Dhi (px rows)
            const char* B2h = smc + W1_OFF;            // W1 hi (m rows)
            const int prb = (pxt * 16 + gr) * 144, prb8 = prb + 1152;
            #pragma unroll 2
            for (int kt = 0; kt < 8; kt++) {
                const int wpA = (kt >> 2) * 9216 + (kt & 3) * 32 + q * 4;
                const int wpB = (kt >> 2) * 9216 + (kt & 3) * 32 + q * 4;
                u32 ah[4];
                ah[0] = *(const u32*)(A2 + wpA + prb);
                ah[1] = *(const u32*)(A2 + wpA + prb8);
                ah[2] = *(const u32*)(A2 + wpA + prb + 16);
                ah[3] = *(const u32*)(A2 + wpA + prb8 + 16);
                #pragma unroll
                for (int j = 0; j < 4; j++) {
                    int nb2 = ((npair * 4 + j) * 8 + gr) * 144;
                    u32 bh2[2];
                    bh2[0] = *(const u32*)(B2h + wpB + nb2);
                    bh2[1] = *(const u32*)(B2h + wpB + nb2 + 16);
                    mma_f16(acc2[j], ah, bh2);
                }
            }
            // fused attention partials: s[px] += w2[m]*relu(h + bt1)
            float p0 = 0.f, p8 = 0.f;
            #pragma unroll
            for (int j = 0; j < 4; j++) {
                p0 += w2x[j] * fmaxf(acc2[j][0] + b1x[j], 0.f)
                    + w2y[j] * fmaxf(acc2[j][1] + b1y[j], 0.f);
                p8 += w2x[j] * fmaxf(acc2[j][2] + b1x[j], 0.f)
                    + w2y[j] * fmaxf(acc2[j][3] + b1y[j], 0.f);
            }
            p0 += __shfl_xor_sync(0xffffffffu, p0, 1);
            p0 += __shfl_xor_sync(0xffffffffu, p0, 2);
            p8 += __shfl_xor_sync(0xffffffffu, p8, 1);
            p8 += __shfl_xor_sync(0xffffffffu, p8, 2);
            if (q == 0) {
                atomicAdd(&sS[br * 64 + pxt * 16 + gr], p0);
                atomicAdd(&sS[br * 64 + pxt * 16 + gr + 8], p8);
            }
        }
        __syncthreads();   // D reads + sS done

        // ---- sigmoid + TIR stages raw D into sDt ----
        {
            if (t < 128) sA[t] = 1.f / (1.f + __expf(-(sS[t] + bt2v)));
            if (br == 1) {
                float* sDt = (float*)smc;           // [o*65 + px]
                float* d0 = sDt + (rbase + gr) * 65;
                float* d1 = sDt + (rbase + gr + 8) * 65;
                #pragma unroll
                for (int nt = 0; nt < 8; nt++) {
                    int c0 = nt * 8 + 2 * q;
                    d0[c0]     = acc[nt][0];
                    d0[c0 + 1] = acc[nt][1];
                    d1[c0]     = acc[nt][2];
                    d1[c0 + 1] = acc[nt][3];
                }
            }
        }
        __syncthreads();

        // ---- fuse + store (RGB warps): out = aR*Dr + aT*Dt ----
        if (br == 0) {
            const float* sDt = (const float*)smc;
            const float* d0 = sDt + (rbase + gr) * 65;
            const float* d1 = sDt + (rbase + gr + 8) * 65;
            float* go = out + (size_t)(b * HALF) * NPIX + pix0;
            float* g0 = go + (size_t)(rbase + gr) * NPIX;
            float* g1 = go + (size_t)(rbase + gr + 8) * NPIX;
            #pragma unroll
            for (int nt = 0; nt < 8; nt++) {
                int c0 = nt * 8 + 2 * q;
                float aR0 = sA[c0], aR1 = sA[c0 + 1];
                float aT0 = sA[64 + c0], aT1 = sA[64 + c0 + 1];
                float2 v0, v1;
                v0.x = aR0 * acc[nt][0] + aT0 * d0[c0];
                v0.y = aR1 * acc[nt][1] + aT1 * d0[c0 + 1];
                v1.x = aR0 * acc[nt][2] + aT0 * d1[c0];
                v1.y = aR1 * acc[nt][3] + aT1 * d1[c0 + 1];
                *(float2*)(g0 + c0) = v0;
                *(float2*)(g1 + c0) = v1;
            }
        }
    }
}

extern "C" void kernel_launch(void* const* d_in, const int* in_sizes, int n_in,
                              void* d_out, int out_size) {
    const float* x    = (const float*)d_in[0];
    const float* Wg   = (const float*)d_in[1];
    const float* bg   = (const float*)d_in[2];
    const float* Wrgb = (const float*)d_in[3];
    const float* brgb = (const float*)d_in[4];
    const float* Wtir = (const float*)d_in[5];
    const float* btir = (const float*)d_in[6];
    const float* Wt1  = (const float*)d_in[7];
    const float* bt1  = (const float*)d_in[8];
    const float* Wt2  = (const float*)d_in[9];
    const float* bt2  = (const float*)d_in[10];
    float* out = (float*)d_out;

    gate_pool<<<BDIM * CDIM, 320>>>(x);

    cudaFuncSetAttribute(moe_expert, cudaFuncAttributeMaxDynamicSharedMemorySize, SMEM_BYTES);
    dim3 grid(18, BDIM);
    moe_expert<<<grid, 512, SMEM_BYTES>>>(x, Wg, bg, Wrgb, brgb, Wtir, btir,
                                          Wt1, bt1, Wt2, bt2, out);
}

// round 14
// speedup vs baseline: 1.5421x; 1.0421x over previous
#include <cuda_runtime.h>
#include <cstdint>
#include <math.h>

#define E_EXPERTS 5
#define CDIM      256
#define HALF      128
#define QUART     64
#define BDIM      8
#define NPIX      6400
#define PIX       64

typedef uint32_t u32;
typedef uint16_t u16;

__device__ float g_pooled[BDIM * CDIM];

// ---------- fp16 helpers ----------
__device__ __forceinline__ u16 to_f16(float f) {
    u16 h; asm("cvt.rn.f16.f32 %0, %1;" : "=h"(h) : "f"(f)); return h;
}
// packs (lo -> low half, hi -> high half)
__device__ __forceinline__ u32 pack_f16x2(float lo, float hi) {
    u32 r; asm("cvt.rn.f16x2.f32 %0, %1, %2;" : "=r"(r) : "f"(hi), "f"(lo)); return r;
}

// ---------- warp mma: D(16x8,f32) += A(16x16,f16 row) * B(16x8,f16 col) ----------
__device__ __forceinline__ void mma_f16(float* d, const u32* a, const u32* b) {
    asm volatile("mma.sync.aligned.m16n8k16.row.col.f32.f16.f16.f32 "
        "{%0,%1,%2,%3},{%4,%5,%6,%7},{%8,%9},{%0,%1,%2,%3};"
        : "+f"(d[0]), "+f"(d[1]), "+f"(d[2]), "+f"(d[3])
        : "r"(a[0]), "r"(a[1]), "r"(a[2]), "r"(a[3]), "r"(b[0]), "r"(b[1]));
}

// ---------- ldmatrix x4 transposed (b16) ----------
__device__ __forceinline__ void ldsm_x4_trans(u32* r, u32 saddr) {
    asm volatile("ldmatrix.sync.aligned.m8n8.x4.trans.shared.b16 {%0,%1,%2,%3}, [%4];"
        : "=r"(r[0]), "=r"(r[1]), "=r"(r[2]), "=r"(r[3]) : "r"(saddr));
}

// ======================= gate kernel 1 (pool) =======================
__global__ void __launch_bounds__(320) gate_pool(const float* __restrict__ x) {
    int bc = blockIdx.x;
    const float4* p4 = (const float4*)(x + (size_t)bc * NPIX);
    float s = 0.f;
    #pragma unroll
    for (int k = 0; k < 5; k++) {             // 1600 float4 = 320 x 5 exactly
        float4 v = __ldg(p4 + k * 320 + threadIdx.x);
        s += (v.x + v.y) + (v.z + v.w);
    }
    __shared__ float red[10];
    #pragma unroll
    for (int o = 16; o; o >>= 1) s += __shfl_down_sync(0xffffffffu, s, o);
    if ((threadIdx.x & 31) == 0) red[threadIdx.x >> 5] = s;
    __syncthreads();
    if (threadIdx.x < 32) {
        float v = (threadIdx.x < 10) ? red[threadIdx.x] : 0.f;
        #pragma unroll
        for (int o = 8; o; o >>= 1) v += __shfl_down_sync(0xffffffffu, v, o);
        if (threadIdx.x == 0) g_pooled[bc] = v * (1.0f / (float)NPIX);
    }
}

// ======================= smem layout (bytes) =======================
// xhi: split-row fp16, swizzled: per branch 2 planes x 64 px-rows x 144B;
//      byte-within-row' = byte ^ ((px>>3 & 7) << 4)  (conflict-free stores+loads)
// Dhi: TRANSPOSED: per branch 128 channel-rows x 144B (64 px x 2B, pad);
//      consumed by ldmatrix.x4.trans as GEMM2 A operand.
// Region A (36864B), time-multiplexed per tile:
//   phase 1: xhi(br) = br*18432 ; phase 2: Dhi (same offsets) ;
//   phase 3: sDt fp32 [o*65+px] (33280B)
// W  : W_OFF + br*36864  (W' = W + I, 2 planes x 128 rows x 144B)
// W1 : W1_OFF            (2 planes x 64 rows x 144B)
// sA : 128 f32 @ SA_OFF;  sS : 128 f32 @ SS_OFF (also gate logits at start)
#define W_OFF    36864
#define W1_OFF   110592
#define SA_OFF   129024
#define SS_OFF   129536
#define SMEM_BYTES 130048

__global__ void __launch_bounds__(512, 1) moe_expert(
    const float* __restrict__ x,
    const float* __restrict__ Wg,   const float* __restrict__ bg,
    const float* __restrict__ Wrgb, const float* __restrict__ brgb,
    const float* __restrict__ Wtir, const float* __restrict__ btir,
    const float* __restrict__ Wt1,  const float* __restrict__ bt1,
    const float* __restrict__ Wt2,  const float* __restrict__ bt2,
    float* __restrict__ out)
{
    extern __shared__ char smc[];
    float* sA = (float*)(smc + SA_OFF);
    float* sS = (float*)(smc + SS_OFF);

    const int t    = threadIdx.x;
    const int w    = t >> 5;
    const int lane = t & 31;
    const int gr   = lane >> 2;
    const int q    = lane & 3;
    const int br   = w >> 3;            // branch: 0=RGB, 1=TIR
    const int msub = w & 7;
    const int rbase = msub * 16;        // GEMM1 o-rows

    const int b = blockIdx.y;

    // ---- inline gate: warp e computes logit e; argmax (strict >, first max) ----
    {
        if (w < E_EXPERTS) {
            const float* pw = Wg + w * CDIM;
            const float* pp = g_pooled + b * CDIM;
            float s = 0.f;
            #pragma unroll
            for (int c = lane; c < CDIM; c += 32) s += pp[c] * pw[c];
            #pragma unroll
            for (int o = 16; o; o >>= 1) s += __shfl_down_sync(0xffffffffu, s, o);
            if (lane == 0) sS[w] = s + __ldg(bg + w);
        }
    }
    __syncthreads();
    int e = 0;
    {
        float best = sS[0];
        #pragma unroll
        for (int i = 1; i < E_EXPERTS; i++) {
            float v = sS[i];
            if (v > best) { best = v; e = i; }
        }
    }

    // 18 blocks/batch: 10x6 + 8x5 = 100 tiles of 64 px (144 blocks = 1 wave)
    const int ib    = blockIdx.x;
    const int tile0 = ib < 10 ? ib * 6 : 60 + (ib - 10) * 5;
    const int tcnt  = ib < 10 ? 6 : 5;

    // ---- hoisted per-thread constants ----
    const float bz0 = __ldg((br ? btir : brgb) + e * HALF + rbase + gr);
    const float bz1 = __ldg((br ? btir : brgb) + e * HALF + rbase + gr + 8);
    // GEMM2': pxt = px 16-tile (0..3), npair selects 4 n8 (m) tiles
    const int   pxt   = msub >> 1;
    const int   npair = msub & 1;
    float w2x[4], w2y[4], b1x[4], b1y[4];
    #pragma unroll
    for (int j = 0; j < 4; j++) {
        int m0 = (npair * 4 + j) * 8 + 2 * q;
        w2x[j] = __ldg(Wt2 + e * QUART + m0);
        w2y[j] = __ldg(Wt2 + e * QUART + m0 + 1);
        b1x[j] = __ldg(bt1 + e * QUART + m0);
        b1y[j] = __ldg(bt1 + e * QUART + m0 + 1);
    }
    const float bt2v = __ldg(bt2 + e);

    // ------------ prologue: W' = W + I, W1 -> fp16 in smem ------------
    #pragma unroll
    for (int br2 = 0; br2 < 2; br2++) {
        const float* gW = (br2 ? Wtir : Wrgb) + (size_t)e * HALF * HALF;
        char* bh = smc + W_OFF + br2 * 36864;
        #pragma unroll 4
        for (int it = 0; it < 16; it++) {
            int lin = it * 512 + t;            // 8192 = 128 o x 64 c-pairs
            int o = lin >> 6, c0 = (lin & 63) * 2;
            float2 v = __ldg((const float2*)(gW + o * 128 + c0));
            float vx = v.x + ((o == c0)     ? 1.f : 0.f);   // residual fold
            float vy = v.y + ((o == c0 + 1) ? 1.f : 0.f);
            int addr = (c0 >> 6) * 18432 + o * 144 + (c0 & 63) * 2;
            *(u32*)(bh + addr) = pack_f16x2(vx, vy);
        }
    }
    {
        const float* g1 = Wt1 + (size_t)e * QUART * HALF;
        char* bh = smc + W1_OFF;
        #pragma unroll 4
        for (int it = 0; it < 8; it++) {
            int lin = it * 512 + t;            // 4096 = 64 m x 64 c-pairs
            int m = lin >> 6, c0 = (lin & 63) * 2;
            float2 v = __ldg((const float2*)(g1 + m * 128 + c0));
            int addr = (c0 >> 6) * 9216 + m * 144 + (c0 & 63) * 2;
            *(u32*)(bh + addr) = pack_f16x2(v.x, v.y);
        }
    }

    // ---- Bx builder mapping ----
    const int cp8 = t >> 3;                       // 0..63
    const int sub = t & 7;

    // ---- GEMM2 A ldmatrix lane base (transposed Dhi) ----
    const int l2   = lane & 7;
    const int tl   = lane >> 3;
    const int arow = l2 + ((tl & 2) ? 8 : 0);            // channel row within 16
    const int acol = pxt * 32 + ((tl & 1) ? 16 : 0);     // px byte offset
    const u32 dsm_base = (u32)__cvta_generic_to_shared(smc + br * 18432)
                       + (u32)(arow * 144 + acol);

    for (int tt = 0; tt < tcnt; tt++) {
        const int pix0 = (tile0 + tt) * PIX;
        __syncthreads();   // region A free (covers prologue + gate on tt=0)

        // ---- build xhi fp16 tile (coalesced LDG + swizzled conflict-free STS) ----
        #pragma unroll
        for (int it = 0; it < 2; it++) {
            const int cpv = cp8 + it * 64;                 // channel pair
            const int c0b = 2 * cpv;
            char* bh = smc + it * 18432 + ((c0b & 64) ? 9216 : 0);
            const int cin = (c0b & 63) * 2;
            const float* g0 = x + ((size_t)(b * CDIM + c0b)) * NPIX + pix0;
            #pragma unroll
            for (int j = 0; j < 2; j++) {
                float4 a0 = __ldg((const float4*)(g0 + sub * 4 + j * 32));
                float4 a1 = __ldg((const float4*)(g0 + NPIX + sub * 4 + j * 32));
                int px0 = sub * 4 + j * 32;
                int cinx = cin ^ ((((px0 >> 3) & 7) << 4));   // same for px0..px0+3
                *(u32*)(bh + (px0    ) * 144 + cinx) = pack_f16x2(a0.x, a1.x);
                *(u32*)(bh + (px0 + 1) * 144 + cinx) = pack_f16x2(a0.y, a1.y);
                *(u32*)(bh + (px0 + 2) * 144 + cinx) = pack_f16x2(a0.z, a1.z);
                *(u32*)(bh + (px0 + 3) * 144 + cinx) = pack_f16x2(a0.w, a1.w);
            }
        }
        __syncthreads();

        // ---- GEMM1: acc[8][4] = W'hi@xhi over N=64 (residual inside W') ----
        float acc[8][4];
        #pragma unroll
        for (int nt = 0; nt < 8; nt++)
            #pragma unroll
            for (int i = 0; i < 4; i++) acc[nt][i] = 0.f;
        {
            const char* Ah = smc + W_OFF + br * 36864;
            const char* Bh = smc + br * 18432;
            const int rb = (rbase + gr) * 144, rb8 = rb + 1152;
            #pragma unroll 2
            for (int kt = 0; kt < 8; kt++) {
                const int wp = (kt >> 2) * 18432 + (kt & 3) * 32 + q * 4;
                const int bplane = (kt >> 2) * 9216;
                const int bbyte  = (kt & 3) * 32 + q * 4;
                u32 ah[4];
                ah[0] = *(const u32*)(Ah + wp + rb);
                ah[1] = *(const u32*)(Ah + wp + rb8);
                ah[2] = *(const u32*)(Ah + wp + rb + 16);
                ah[3] = *(const u32*)(Ah + wp + rb8 + 16);
                #pragma unroll
                for (int nt = 0; nt < 8; nt++) {
                    const int swzn = (nt & 7) << 4;
                    const int nb2 = (nt * 8 + gr) * 144 + bplane;
                    u32 bh2[2];
                    bh2[0] = *(const u32*)(Bh + nb2 + (bbyte ^ swzn));
                    bh2[1] = *(const u32*)(Bh + nb2 + ((bbyte + 16) ^ swzn));
                    mma_f16(acc[nt], ah, bh2);
                }
            }
        }
        // epilogue: + bias only (residual already in W')
        #pragma unroll
        for (int nt = 0; nt < 8; nt++) {
            acc[nt][0] += bz0;
            acc[nt][1] += bz0;
            acc[nt][2] += bz1;
            acc[nt][3] += bz1;
        }
        __syncthreads();   // xhi reads done

        // ---- store Dhi TRANSPOSED (rows=channel, cols=px); zero sS ----
        {
            char* Dh = smc + br * 18432;
            char* d0 = Dh + (rbase + gr) * 144;
            char* d1 = d0 + 8 * 144;
            #pragma unroll
            for (int nt = 0; nt < 8; nt++) {
                int pxb = (nt * 8 + 2 * q) * 2;
                *(u32*)(d0 + pxb) = pack_f16x2(acc[nt][0], acc[nt][1]);
                *(u32*)(d1 + pxb) = pack_f16x2(acc[nt][2], acc[nt][3]);
            }
            if (t < 128) sS[t] = 0.f;
        }
        __syncthreads();

        // ---- GEMM2': h^T = Dhi@W1hi^T (A via ldmatrix.trans); fused attention ----
        {
            float acc2[4][4];
            #pragma unroll
            for (int j = 0; j < 4; j++)
                #pragma unroll
                for (int i = 0; i < 4; i++) acc2[j][i] = 0.f;

            const char* B2h = smc + W1_OFF;            // W1 hi (m rows)
            #pragma unroll 2
            for (int kt = 0; kt < 8; kt++) {
                u32 ah[4];
                ldsm_x4_trans(ah, dsm_base + (u32)(kt * 16 * 144));
                const int wpB = (kt >> 2) * 9216 + (kt & 3) * 32 + q * 4;
                #pragma unroll
                for (int j = 0; j < 4; j++) {
                    int nb2 = ((npair * 4 + j) * 8 + gr) * 144;
                    u32 bh2[2];
                    bh2[0] = *(const u32*)(B2h + wpB + nb2);
                    bh2[1] = *(const u32*)(B2h + wpB + nb2 + 16);
                    mma_f16(acc2[j], ah, bh2);
                }
            }
            // fused attention partials: s[px] += w2[m]*relu(h + bt1)
            float p0 = 0.f, p8 = 0.f;
            #pragma unroll
            for (int j = 0; j < 4; j++) {
                p0 += w2x[j] * fmaxf(acc2[j][0] + b1x[j], 0.f)
                    + w2y[j] * fmaxf(acc2[j][1] + b1y[j], 0.f);
                p8 += w2x[j] * fmaxf(acc2[j][2] + b1x[j], 0.f)
                    + w2y[j] * fmaxf(acc2[j][3] + b1y[j], 0.f);
            }
            p0 += __shfl_xor_sync(0xffffffffu, p0, 1);
            p0 += __shfl_xor_sync(0xffffffffu, p0, 2);
            p8 += __shfl_xor_sync(0xffffffffu, p8, 1);
            p8 += __shfl_xor_sync(0xffffffffu, p8, 2);
            if (q == 0) {
                atomicAdd(&sS[br * 64 + pxt * 16 + gr], p0);
                atomicAdd(&sS[br * 64 + pxt * 16 + gr + 8], p8);
            }
        }
        __syncthreads();   // D reads + sS done

        // ---- sigmoid + TIR stages raw D into sDt ----
        {
            if (t < 128) sA[t] = 1.f / (1.f + __expf(-(sS[t] + bt2v)));
            if (br == 1) {
                float* sDt = (float*)smc;           // [o*65 + px]
                float* d0 = sDt + (rbase + gr) * 65;
                float* d1 = sDt + (rbase + gr + 8) * 65;
                #pragma unroll
                for (int nt = 0; nt < 8; nt++) {
                    int c0 = nt * 8 + 2 * q;
                    d0[c0]     = acc[nt][0];
                    d0[c0 + 1] = acc[nt][1];
                    d1[c0]     = acc[nt][2];
                    d1[c0 + 1] = acc[nt][3];
                }
            }
        }
        __syncthreads();

        // ---- fuse + store (RGB warps): out = aR*Dr + aT*Dt ----
        if (br == 0) {
            const float* sDt = (const float*)smc;
            const float* d0 = sDt + (rbase + gr) * 65;
            const float* d1 = sDt + (rbase + gr + 8) * 65;
            float* go = out + (size_t)(b * HALF) * NPIX + pix0;
            float* g0 = go + (size_t)(rbase + gr) * NPIX;
            float* g1 = go + (size_t)(rbase + gr + 8) * NPIX;
            #pragma unroll
            for (int nt = 0; nt < 8; nt++) {
                int c0 = nt * 8 + 2 * q;
                float aR0 = sA[c0], aR1 = sA[c0 + 1];
                float aT0 = sA[64 + c0], aT1 = sA[64 + c0 + 1];
                float2 v0, v1;
                v0.x = aR0 * acc[nt][0] + aT0 * d0[c0];
                v0.y = aR1 * acc[nt][1] + aT1 * d0[c0 + 1];
                v1.x = aR0 * acc[nt][2] + aT0 * d1[c0];
                v1.y = aR1 * acc[nt][3] + aT1 * d1[c0 + 1];
                *(float2*)(g0 + c0) = v0;
                *(float2*)(g1 + c0) = v1;
            }
        }
    }
}

extern "C" void kernel_launch(void* const* d_in, const int* in_sizes, int n_in,
                              void* d_out, int out_size) {
    const float* x    = (const float*)d_in[0];
    const float* Wg   = (const float*)d_in[1];
    const float* bg   = (const float*)d_in[2];
    const float* Wrgb = (const float*)d_in[3];
    const float* brgb = (const float*)d_in[4];
    const float* Wtir = (const float*)d_in[5];
    const float* btir = (const float*)d_in[6];
    const float* Wt1  = (const float*)d_in[7];
    const float* bt1  = (const float*)d_in[8];
    const float* Wt2  = (const float*)d_in[9];
    const float* bt2  = (const float*)d_in[10];
    float* out = (float*)d_out;

    gate_pool<<<BDIM * CDIM, 320>>>(x);

    cudaFuncSetAttribute(moe_expert, cudaFuncAttributeMaxDynamicSharedMemorySize, SMEM_BYTES);
    dim3 grid(18, BDIM);
    moe_expert<<<grid, 512, SMEM_BYTES>>>(x, Wg, bg, Wrgb, brgb, Wtir, btir,
                                          Wt1, bt1, Wt2, bt2, out);
}